// round 13
// baseline (speedup 1.0000x reference)
#include <cuda_runtime.h>
#include <cuda_fp16.h>
#include <math.h>

// Problem dims
#define TB   262144   // T*B = 256*1024
#define TT   256
#define BB   1024
#define NOUT 19

// ---------------- scratch (static device memory; no allocs) ----------------
__device__ float g_h1[TB * 128];
__device__ float g_h2[TB * 32];
__device__ float g_h3[TB * 128];
__device__ float g_xg[TB * 512];
__device__ float g_hs[TB * 128];
__device__ unsigned g_WhhFragH[32 * 8 * 32 * 4];  // [mtile][ks][lane][reg], fp16x2
__device__ float g_bg[512];
__device__ float g_Whead[NOUT * 128];
__device__ float g_bhead[NOUT];

// ---------------- packed f32x2 helpers ----------------
typedef unsigned long long ull;
__device__ __forceinline__ ull pack2(float lo, float hi) {
    ull r; asm("mov.b64 %0, {%1, %2};" : "=l"(r) : "f"(lo), "f"(hi)); return r;
}
__device__ __forceinline__ void unpack2(ull p, float& lo, float& hi) {
    asm("mov.b64 {%0, %1}, %2;" : "=f"(lo), "=f"(hi) : "l"(p));
}
__device__ __forceinline__ ull ffma2(ull a, ull b, ull c) {
    ull d; asm("fma.rn.f32x2 %0, %1, %2, %3;" : "=l"(d) : "l"(a), "l"(b), "l"(c));
    return d;
}

// ---------------- tf32 helpers (feedforward GEMMs) ----------------
__device__ __forceinline__ unsigned tf32_of(float f) {
    unsigned r; asm("cvt.rna.tf32.f32 %0, %1;" : "=r"(r) : "f"(f)); return r;
}
__device__ __forceinline__ void mma_tf32(float* d, const unsigned* a, const unsigned* b) {
    asm volatile(
        "mma.sync.aligned.m16n8k8.row.col.f32.tf32.tf32.f32 "
        "{%0,%1,%2,%3}, {%4,%5,%6,%7}, {%8,%9}, {%0,%1,%2,%3};"
        : "+f"(d[0]), "+f"(d[1]), "+f"(d[2]), "+f"(d[3])
        : "r"(a[0]), "r"(a[1]), "r"(a[2]), "r"(a[3]), "r"(b[0]), "r"(b[1]));
}

// ---------------- fp16 mma (LSTM recurrence) ----------------
__device__ __forceinline__ void mma_f16(float* d, const unsigned* a, const unsigned* b) {
    asm volatile(
        "mma.sync.aligned.m16n8k16.row.col.f32.f16.f16.f32 "
        "{%0,%1,%2,%3}, {%4,%5,%6,%7}, {%8,%9}, {%0,%1,%2,%3};"
        : "+f"(d[0]), "+f"(d[1]), "+f"(d[2]), "+f"(d[3])
        : "r"(a[0]), "r"(a[1]), "r"(a[2]), "r"(a[3]), "r"(b[0]), "r"(b[1]));
}

// ---------------- fast activations ----------------
__device__ __forceinline__ float sigmoid_f(float x) {
    return __fdividef(1.f, 1.f + __expf(-x));
}
__device__ __forceinline__ float tanh_f(float x) {
    float e = __expf(-2.f * fabsf(x));
    float r = __fdividef(1.f - e, 1.f + e);
    return copysignf(r, x);
}

// ---------------- prepack ----------------
// g_WhhFragH[mt][ks][lane][r]: exact mma.m16n8k16 fp16 A-fragment order (row-major A):
//   gg = lane>>2, tg = lane&3
//   r0 = (row=16mt+gg,   cols 16ks+2tg, +1)    r1 = (row+8, same cols)
//   r2 = (row,           cols 16ks+8+2tg, +1)  r3 = (row+8, same cols)
// Each unsigned packs two fp16 from adjacent k columns (low = first).
__global__ void prepack_kernel(const float* __restrict__ Whh,
                               const float* __restrict__ bih,
                               const float* __restrict__ bhh,
                               const float* __restrict__ Wa,
                               const float* __restrict__ ba,
                               const float* __restrict__ Wc,
                               const float* __restrict__ bc) {
    int t = blockIdx.x * blockDim.x + threadIdx.x;
    int stride = gridDim.x * blockDim.x;
    for (int i = t; i < 32 * 8 * 32 * 4; i += stride) {
        int r    = i & 3;
        int lane = (i >> 2) & 31;
        int ks   = (i >> 7) & 7;
        int mt   = i >> 10;
        int gg = lane >> 2, tg = lane & 3;
        int row = mt * 16 + gg + ((r & 1) ? 8 : 0);
        int col = ks * 16 + 2 * tg + ((r & 2) ? 8 : 0);
        __half2 hv = __floats2half2_rn(Whh[row * 128 + col], Whh[row * 128 + col + 1]);
        g_WhhFragH[i] = *(unsigned*)&hv;
    }
    if (t < 512) g_bg[t] = bih[t] + bhh[t];
    for (int i = t; i < NOUT * 128; i += stride) {
        int n = i / 128, k = i % 128;
        g_Whead[i] = (n < 18) ? Wa[n * 128 + k] : Wc[k];
    }
    if (t < NOUT) g_bhead[t] = (t < 18) ? ba[t] : bc[0];
}

// ================= TF32 tensor-core GEMM (feedforward) =================
template<int BN, int WARPS_M, int WARPS_N, bool RELU>
__global__ void __launch_bounds__(32 * WARPS_M * WARPS_N, 2)
tf32_gemm(const float* __restrict__ A, const float* __restrict__ W,
          const float* __restrict__ bias, float* __restrict__ C, int K) {
    constexpr int BM = 128;
    constexpr int BK = 32;
    constexpr int THREADS = 32 * WARPS_M * WARPS_N;
    constexpr int MT = (BM / WARPS_M) / 16;
    constexpr int NT = (BN / WARPS_N) / 8;

    __shared__ unsigned As[BM / 16][BK / 8][32][4];
    __shared__ unsigned Bs[BN / 8][BK / 16][32][4];

    const int tid  = threadIdx.x;
    const int lane = tid & 31;
    const int w    = tid >> 5;
    const int wm   = w / WARPS_N;
    const int wn   = w % WARPS_N;
    const int bm   = blockIdx.x * BM;
    const int bn   = blockIdx.y * BN;
    const int g    = lane >> 2;
    const int tig  = lane & 3;

    float acc[MT][NT][4];
#pragma unroll
    for (int i = 0; i < MT; i++)
#pragma unroll
        for (int j = 0; j < NT; j++)
#pragma unroll
            for (int r = 0; r < 4; r++) acc[i][j][r] = 0.f;

    for (int k0 = 0; k0 < K; k0 += BK) {
        constexpr int AV4 = BM * BK / 4;
#pragma unroll
        for (int it = 0; it < AV4 / THREADS; it++) {
            int idx = tid + it * THREADS;
            int row = idx >> 3;
            int c4  = idx & 7;
            float4 v = *(const float4*)(A + (size_t)(bm + row) * K + k0 + c4 * 4);
            int mt = row >> 4, r = row & 15;
            float vv[4] = {v.x, v.y, v.z, v.w};
#pragma unroll
            for (int j = 0; j < 4; j++) {
                int col = c4 * 4 + j;
                int kt = col >> 3, c = col & 7;
                As[mt][kt][(r & 7) * 4 + (c & 3)][(r >> 3) + 2 * (c >> 2)] = tf32_of(vv[j]);
            }
        }
        constexpr int BV4 = BN * BK / 4;
#pragma unroll
        for (int it = 0; it < (BV4 + THREADS - 1) / THREADS; it++) {
            int idx = tid + it * THREADS;
            if ((BV4 % THREADS == 0) || idx < BV4) {
                int n  = idx >> 3;
                int c4 = idx & 7;
                float4 v = *(const float4*)(W + (size_t)(bn + n) * K + k0 + c4 * 4);
                int nt = n >> 3, gg = n & 7;
                float vv[4] = {v.x, v.y, v.z, v.w};
#pragma unroll
                for (int j = 0; j < 4; j++) {
                    int k = c4 * 4 + j;
                    int kblk = k >> 4, kk = k & 15;
                    Bs[nt][kblk][gg * 4 + (kk & 3)][((kk >> 3) << 1) + ((kk & 7) >> 2)] = tf32_of(vv[j]);
                }
            }
        }
        __syncthreads();

#pragma unroll
        for (int kt = 0; kt < 4; kt++) {
            unsigned a[MT][4];
#pragma unroll
            for (int mt = 0; mt < MT; mt++)
                *(uint4*)a[mt] = *(const uint4*)&As[wm * MT + mt][kt][lane][0];
            unsigned b[NT][2];
#pragma unroll
            for (int nt = 0; nt < NT; nt++)
                *(uint2*)b[nt] = *(const uint2*)&Bs[wn * NT + nt][kt >> 1][lane][(kt & 1) * 2];
#pragma unroll
            for (int mt = 0; mt < MT; mt++)
#pragma unroll
                for (int nt = 0; nt < NT; nt++)
                    mma_tf32(acc[mt][nt], a[mt], b[nt]);
        }
        __syncthreads();
    }

#pragma unroll
    for (int mt = 0; mt < MT; mt++) {
#pragma unroll
        for (int nt = 0; nt < NT; nt++) {
            int col = bn + wn * (NT * 8) + nt * 8 + 2 * tig;
            int row0 = bm + wm * (MT * 16) + mt * 16 + g;
            float b0 = bias[col], b1 = bias[col + 1];
            float v0 = acc[mt][nt][0] + b0, v1 = acc[mt][nt][1] + b1;
            float v2 = acc[mt][nt][2] + b0, v3 = acc[mt][nt][3] + b1;
            if (RELU) {
                v0 = fmaxf(v0, 0.f); v1 = fmaxf(v1, 0.f);
                v2 = fmaxf(v2, 0.f); v3 = fmaxf(v3, 0.f);
            }
            int N_total = gridDim.y * BN;
            *(float2*)(C + (size_t)row0 * N_total + col)       = make_float2(v0, v1);
            *(float2*)(C + (size_t)(row0 + 8) * N_total + col) = make_float2(v2, v3);
        }
    }
}

// ---------------- scalar f32x2 GEMM (heads only, N=19) ----------------
template<int BM, int BN, int BK, int TM, int TN, bool RELU, bool NGUARD>
__global__ void __launch_bounds__((BM / TM) * (BN / TN))
gemm_kernel(const float* __restrict__ A, const float* __restrict__ W,
            const float* __restrict__ bias, float* __restrict__ C,
            int N, int K, int ldc) {
    constexpr int THREADS = (BM / TM) * (BN / TN);
    constexpr int BNQ = BN / TN;
    __shared__ __align__(16) float As[BK][BM + 4];
    __shared__ __align__(16) float Ws[BK][BN + 4];

    const int tid = threadIdx.x;
    const int bm = blockIdx.x * BM;
    const int bn = blockIdx.y * BN;
    const int tx = tid % BNQ;
    const int ty = tid / BNQ;

    ull acc2[TM / 2][TN];
#pragma unroll
    for (int i = 0; i < TM / 2; i++)
#pragma unroll
        for (int j = 0; j < TN; j++) acc2[i][j] = 0ull;

    for (int k0 = 0; k0 < K; k0 += BK) {
        constexpr int AV = BM * BK / 4;
#pragma unroll
        for (int i = 0; i < AV / THREADS; i++) {
            int idx = tid + i * THREADS;
            int row = idx / (BK / 4);
            int c4 = idx % (BK / 4);
            float4 v = *(const float4*)(A + (size_t)(bm + row) * K + k0 + c4 * 4);
            As[c4 * 4 + 0][row] = v.x;
            As[c4 * 4 + 1][row] = v.y;
            As[c4 * 4 + 2][row] = v.z;
            As[c4 * 4 + 3][row] = v.w;
        }
        constexpr int WV = BN * BK / 4;
#pragma unroll
        for (int i = 0; i < (WV + THREADS - 1) / THREADS; i++) {
            int idx = tid + i * THREADS;
            if ((WV % THREADS == 0) || idx < WV) {
                int row = idx / (BK / 4);
                int c4 = idx % (BK / 4);
                float4 v;
                if (!NGUARD || (bn + row) < N)
                    v = *(const float4*)(W + (size_t)(bn + row) * K + k0 + c4 * 4);
                else
                    v = make_float4(0.f, 0.f, 0.f, 0.f);
                Ws[c4 * 4 + 0][row] = v.x;
                Ws[c4 * 4 + 1][row] = v.y;
                Ws[c4 * 4 + 2][row] = v.z;
                Ws[c4 * 4 + 3][row] = v.w;
            }
        }
        __syncthreads();
#pragma unroll
        for (int kk = 0; kk < BK; kk++) {
            ull a2[TM / 2];
#pragma unroll
            for (int i2 = 0; i2 < TM / 2; i2++)
                a2[i2] = *(const ull*)&As[kk][ty * TM + 2 * i2];
            float br[TN];
#pragma unroll
            for (int j = 0; j < TN; j++) br[j] = Ws[kk][tx * TN + j];
            ull b2[TN];
#pragma unroll
            for (int j = 0; j < TN; j++) b2[j] = pack2(br[j], br[j]);
#pragma unroll
            for (int i2 = 0; i2 < TM / 2; i2++)
#pragma unroll
                for (int j = 0; j < TN; j++)
                    acc2[i2][j] = ffma2(a2[i2], b2[j], acc2[i2][j]);
        }
        __syncthreads();
    }
#pragma unroll
    for (int j = 0; j < TN; j++) {
        int n = bn + tx * TN + j;
        if (NGUARD && n >= N) continue;
        float bv = bias[n];
#pragma unroll
        for (int i2 = 0; i2 < TM / 2; i2++) {
            float v0, v1;
            unpack2(acc2[i2][j], v0, v1);
            v0 += bv; v1 += bv;
            if (RELU) { v0 = fmaxf(v0, 0.f); v1 = fmaxf(v1, 0.f); }
            C[(size_t)(bm + ty * TM + 2 * i2 + 0) * ldc + n] = v0;
            C[(size_t)(bm + ty * TM + 2 * i2 + 1) * ldc + n] = v1;
        }
    }
}

// ========== persistent tensor-core LSTM (fp16 m16n8k16, all-resident Whh) ===
// 128 CTAs x 512 threads (16 warps); CTA owns 8 batch rows for all 256 steps.
// G[512 gates, 8 batch] per step via mma.m16n8k16 (gates=M, batch=N, k=128).
// ALL 32 Whh tiles resident in smem as fp16 fragments (128 KB total).
// Warp w computes m-tiles {w, 16+w}:
//   w<8 : i-gates + g-gates (same j)  -> keeps c in registers
//   w>=8: f-gates + o-gates (same j)  -> exchange via 8KB smem
// h kept in smem as fp16x2 packed hp[k/2][b] (k-pairs, per batch col).
#define LSTM3_SMEM (32 * 4096 + 512 * 4 + 2048 * 4)   // frags + hp + ex

__global__ void __launch_bounds__(512, 1)
lstm_tc_kernel(const float* __restrict__ xg, const float* __restrict__ done,
               const float* __restrict__ h0, const float* __restrict__ c0,
               float* __restrict__ hs, const unsigned* __restrict__ frag) {
    extern __shared__ unsigned smu[];
    unsigned* smA = smu;                        // [32 tiles][8 ks][32 lanes][4]
    unsigned* hp  = smu + 32768;                // [64 k2][8 b] fp16x2
    float*    ex  = (float*)(smu + 32768 + 512);// [2][128 j][8 b]

    const int tid  = threadIdx.x;
    const int w    = tid >> 5;
    const int lane = tid & 31;
    const int gg   = lane >> 2;
    const int tg   = lane & 3;
    const int bb0  = blockIdx.x * 8;

    // cooperative load of ALL fragment tiles (128 KB, coalesced)
    {
        const uint4* src = (const uint4*)frag;
        uint4* dst = (uint4*)smA;
        for (int i = tid; i < 8192; i += 512) dst[i] = src[i];
    }
    // h init: h0 masked by done[0], fp16-rounded, packed by k-pairs
    __half* hview = (__half*)hp;
    for (int i = tid; i < 1024; i += 512) {
        int j = i >> 3, b = i & 7;
        float m = 1.f - done[bb0 + b];
        hview[(j >> 1) * 16 + 2 * b + (j & 1)] = __float2half_rn(h0[(bb0 + b) * 128 + j] * m);
    }
    __syncthreads();

    const int j0 = 16 * w + gg;         // cell row base (valid w<8)
    const int bA = bb0 + 2 * tg;
    const int bB = bA + 1;

    float c[4] = {0.f, 0.f, 0.f, 0.f};
    if (w < 8) {
        float mA = 1.f - done[bA], mB = 1.f - done[bB];
        c[0] = c0[bA * 128 + j0] * mA;
        c[1] = c0[bB * 128 + j0] * mB;
        c[2] = c0[bA * 128 + j0 + 8] * mA;
        c[3] = c0[bB * 128 + j0 + 8] * mB;
    }

    const int n0 = w * 16 + gg;           // tile0 gate index base
    const int n1 = (16 + w) * 16 + gg;    // tile1
    const uint4* smT0 = (const uint4*)(smA + w * 1024);
    const uint4* smT1 = (const uint4*)(smA + (16 + w) * 1024);

    for (int step = 0; step < TT; ++step) {
        // xg for this lane's 8 D-cells (issued early; latency hides under mma)
        const float* xb  = xg + ((size_t)step * BB + bA) * 512;
        const float* xb2 = xb + 512;
        float x0[4], x1[4];
        x0[0] = xb[n0];     x0[1] = xb2[n0];
        x0[2] = xb[n0 + 8]; x0[3] = xb2[n0 + 8];
        x1[0] = xb[n1];     x1[1] = xb2[n1];
        x1[2] = xb[n1 + 8]; x1[3] = xb2[n1 + 8];

        // ---- G = Whh @ h : 8 x k16 fp16 mma per tile ----
        float acc0[4] = {0.f, 0.f, 0.f, 0.f};
        float acc1[4] = {0.f, 0.f, 0.f, 0.f};
#pragma unroll
        for (int ks = 0; ks < 8; ks++) {
            unsigned b_[2];
            b_[0] = hp[(ks * 8 + tg) * 8 + gg];       // k = 16ks+2tg,   +1
            b_[1] = hp[(ks * 8 + 4 + tg) * 8 + gg];   // k = 16ks+8+2tg, +1
            uint4 a0 = smT0[ks * 32 + lane];
            uint4 a1 = smT1[ks * 32 + lane];
            mma_f16(acc0, (const unsigned*)&a0, b_);
            mma_f16(acc1, (const unsigned*)&a1, b_);
        }

        float ig[4], gt[4];
        if (w >= 8) {
            // f = sigmoid(tile w), o = sigmoid(tile 16+w) -> smem exchange
            int jj = (w - 8) * 16 + gg;
#pragma unroll
            for (int r = 0; r < 4; r++) {
                float fv = sigmoid_f(acc0[r] + x0[r]);
                float ov = sigmoid_f(acc1[r] + x1[r]);
                int j = jj + ((r & 2) ? 8 : 0);
                int b = 2 * tg + (r & 1);
                ex[j * 8 + b]        = fv;
                ex[1024 + j * 8 + b] = ov;
            }
        } else {
#pragma unroll
            for (int r = 0; r < 4; r++) {
                ig[r] = sigmoid_f(acc0[r] + x0[r]);   // i-gate
                gt[r] = tanh_f(acc1[r] + x1[r]);      // g-gate
            }
        }
        __syncthreads();

        if (w < 8) {
            float mA2 = 1.f, mB2 = 1.f;
            if (step + 1 < TT) {
                mA2 = 1.f - done[(size_t)(step + 1) * BB + bA];
                mB2 = 1.f - done[(size_t)(step + 1) * BB + bB];
            }
#pragma unroll
            for (int r = 0; r < 4; r++) {
                int j = j0 + ((r & 2) ? 8 : 0);
                int b = 2 * tg + (r & 1);
                float fv = ex[j * 8 + b];
                float ov = ex[1024 + j * 8 + b];
                c[r] = fv * c[r] + ig[r] * gt[r];
                float hv = ov * tanh_f(c[r]);
                hs[((size_t)step * BB + bb0 + b) * 128 + j] = hv;
                float m = (r & 1) ? mB2 : mA2;
                c[r] *= m;
                hview[(j >> 1) * 16 + 2 * b + (j & 1)] = __float2half_rn(hv * m);
            }
        }
        __syncthreads();
    }
}

// ---------------- launch ----------------
extern "C" void kernel_launch(void* const* d_in, const int* in_sizes, int n_in,
                              void* d_out, int out_size) {
    const float* x    = (const float*)d_in[0];
    const float* done = (const float*)d_in[1];
    const float* h0   = (const float*)d_in[2];
    const float* c0   = (const float*)d_in[3];
    const float* W1   = (const float*)d_in[4];
    const float* b1   = (const float*)d_in[5];
    const float* W2   = (const float*)d_in[6];
    const float* b2   = (const float*)d_in[7];
    const float* W3   = (const float*)d_in[8];
    const float* b3   = (const float*)d_in[9];
    const float* Wih  = (const float*)d_in[10];
    const float* Whh  = (const float*)d_in[11];
    const float* bih  = (const float*)d_in[12];
    const float* bhh  = (const float*)d_in[13];
    const float* Wa   = (const float*)d_in[14];
    const float* ba   = (const float*)d_in[15];
    const float* Wc   = (const float*)d_in[16];
    const float* bc   = (const float*)d_in[17];
    float* out = (float*)d_out;

    float *h1, *h2, *h3, *xgp, *hsp, *bg, *whd, *bhd;
    unsigned* fragp;
    cudaGetSymbolAddress((void**)&h1,    g_h1);
    cudaGetSymbolAddress((void**)&h2,    g_h2);
    cudaGetSymbolAddress((void**)&h3,    g_h3);
    cudaGetSymbolAddress((void**)&xgp,   g_xg);
    cudaGetSymbolAddress((void**)&hsp,   g_hs);
    cudaGetSymbolAddress((void**)&fragp, g_WhhFragH);
    cudaGetSymbolAddress((void**)&bg,    g_bg);
    cudaGetSymbolAddress((void**)&whd,   g_Whead);
    cudaGetSymbolAddress((void**)&bhd,   g_bhead);

    static int smem_set = 0;
    if (!smem_set) {
        cudaFuncSetAttribute(lstm_tc_kernel,
                             cudaFuncAttributeMaxDynamicSharedMemorySize,
                             LSTM3_SMEM);
        smem_set = 1;
    }

    prepack_kernel<<<128, 256>>>(Whh, bih, bhh, Wa, ba, Wc, bc);

    // MLP encoder (tf32 tensor cores)
    tf32_gemm<128, 4, 2, true><<<dim3(TB / 128, 1), 256>>>(x,  W1, b1, h1, 128);
    tf32_gemm< 32, 8, 1, true><<<dim3(TB / 128, 1), 256>>>(h1, W2, b2, h2, 128);
    tf32_gemm<128, 4, 2, true><<<dim3(TB / 128, 1), 256>>>(h2, W3, b3, h3, 32);

    // xg = h3 @ Wih^T + (bih+bhh)
    tf32_gemm<256, 2, 4, false><<<dim3(TB / 128, 2), 256>>>(h3, Wih, bg, xgp, 128);

    // Sequential LSTM (fp16 tensor-core recurrence, Whh fully smem-resident)
    lstm_tc_kernel<<<128, 512, LSTM3_SMEM>>>(xgp, done, h0, c0, hsp, fragp);

    // Heads (fp32 scalar, N=19)
    gemm_kernel<128, 32, 32, 8, 2, false, true>
        <<<dim3(TB / 128, 1), 256>>>(hsp, whd, bhd, out, NOUT, 128, NOUT);
}

// round 14
// speedup vs baseline: 1.0719x; 1.0719x over previous
#include <cuda_runtime.h>
#include <cuda_fp16.h>
#include <math.h>

// Problem dims
#define TB   262144   // T*B = 256*1024
#define TT   256
#define BB   1024
#define NOUT 19

// ---------------- scratch (static device memory; no allocs) ----------------
__device__ float g_h1[TB * 128];
__device__ float g_h2[TB * 32];
__device__ float g_h3[TB * 128];
__device__ float g_xg[TB * 512];
__device__ float g_hs[TB * 128];
__device__ unsigned g_WhhFragH[32 * 8 * 32 * 4];  // [mtile][ks][lane][reg], fp16x2
__device__ float g_bg[512];
__device__ float g_Whead[NOUT * 128];
__device__ float g_bhead[NOUT];

// ---------------- packed f32x2 helpers ----------------
typedef unsigned long long ull;
__device__ __forceinline__ ull pack2(float lo, float hi) {
    ull r; asm("mov.b64 %0, {%1, %2};" : "=l"(r) : "f"(lo), "f"(hi)); return r;
}
__device__ __forceinline__ void unpack2(ull p, float& lo, float& hi) {
    asm("mov.b64 {%0, %1}, %2;" : "=f"(lo), "=f"(hi) : "l"(p));
}
__device__ __forceinline__ ull ffma2(ull a, ull b, ull c) {
    ull d; asm("fma.rn.f32x2 %0, %1, %2, %3;" : "=l"(d) : "l"(a), "l"(b), "l"(c));
    return d;
}

// ---------------- tf32 helpers (feedforward GEMMs) ----------------
__device__ __forceinline__ unsigned tf32_of(float f) {
    unsigned r; asm("cvt.rna.tf32.f32 %0, %1;" : "=r"(r) : "f"(f)); return r;
}
__device__ __forceinline__ void mma_tf32(float* d, const unsigned* a, const unsigned* b) {
    asm volatile(
        "mma.sync.aligned.m16n8k8.row.col.f32.tf32.tf32.f32 "
        "{%0,%1,%2,%3}, {%4,%5,%6,%7}, {%8,%9}, {%0,%1,%2,%3};"
        : "+f"(d[0]), "+f"(d[1]), "+f"(d[2]), "+f"(d[3])
        : "r"(a[0]), "r"(a[1]), "r"(a[2]), "r"(a[3]), "r"(b[0]), "r"(b[1]));
}

// ---------------- fp16 mma (LSTM recurrence) ----------------
__device__ __forceinline__ void mma_f16(float* d, const unsigned* a, const unsigned* b) {
    asm volatile(
        "mma.sync.aligned.m16n8k16.row.col.f32.f16.f16.f32 "
        "{%0,%1,%2,%3}, {%4,%5,%6,%7}, {%8,%9}, {%0,%1,%2,%3};"
        : "+f"(d[0]), "+f"(d[1]), "+f"(d[2]), "+f"(d[3])
        : "r"(a[0]), "r"(a[1]), "r"(a[2]), "r"(a[3]), "r"(b[0]), "r"(b[1]));
}

// ---------------- fast activations ----------------
__device__ __forceinline__ float sigmoid_f(float x) {
    return __fdividef(1.f, 1.f + __expf(-x));
}
__device__ __forceinline__ float tanh_f(float x) {
    float e = __expf(-2.f * fabsf(x));
    float r = __fdividef(1.f - e, 1.f + e);
    return copysignf(r, x);
}

// ---------------- prepack ----------------
// Gate-interleaved tile permutation for the LSTM:
//   tile 2w   rows 0..7  = i-gates j in [8w, 8w+8), rows 8..15 = f-gates same j
//   tile 2w+1 rows 0..7  = g-gates same j,          rows 8..15 = o-gates same j
// With the m16n8k16 D-fragment map (d0/d1 = row gg cols 2tg/2tg+1; d2/d3 = row
// gg+8), each thread's accumulators hold i,f (tile 2w) and g,o (tile 2w+1) for
// cells (j=8w+gg, b=2tg / 2tg+1) -> cell update is fully register-local.
// Fragment order (row-major A, fp16x2 per reg):
//   gg=lane>>2, tg=lane&3; lrow = gg + (r&1 ? 8:0); col = 16ks + 2tg + (r&2 ? 8:0)
__global__ void prepack_kernel(const float* __restrict__ Whh,
                               const float* __restrict__ bih,
                               const float* __restrict__ bhh,
                               const float* __restrict__ Wa,
                               const float* __restrict__ ba,
                               const float* __restrict__ Wc,
                               const float* __restrict__ bc) {
    int t = blockIdx.x * blockDim.x + threadIdx.x;
    int stride = gridDim.x * blockDim.x;
    for (int i = t; i < 32 * 8 * 32 * 4; i += stride) {
        int r    = i & 3;
        int lane = (i >> 2) & 31;
        int ks   = (i >> 7) & 7;
        int mt   = i >> 10;
        int gg = lane >> 2, tg = lane & 3;
        int lrow = gg + ((r & 1) ? 8 : 0);
        int col  = ks * 16 + 2 * tg + ((r & 2) ? 8 : 0);
        int wq   = mt >> 1;
        int half = mt & 1;
        int gate = (lrow < 8) ? (half ? 2 : 0) : (half ? 3 : 1);  // i,f,g,o blocks
        int row  = gate * 128 + wq * 8 + (lrow & 7);
        __half2 hv = __floats2half2_rn(Whh[row * 128 + col], Whh[row * 128 + col + 1]);
        g_WhhFragH[i] = *(unsigned*)&hv;
    }
    if (t < 512) g_bg[t] = bih[t] + bhh[t];
    for (int i = t; i < NOUT * 128; i += stride) {
        int n = i / 128, k = i % 128;
        g_Whead[i] = (n < 18) ? Wa[n * 128 + k] : Wc[k];
    }
    if (t < NOUT) g_bhead[t] = (t < 18) ? ba[t] : bc[0];
}

// ================= TF32 tensor-core GEMM (feedforward) =================
template<int BN, int WARPS_M, int WARPS_N, bool RELU>
__global__ void __launch_bounds__(32 * WARPS_M * WARPS_N, 2)
tf32_gemm(const float* __restrict__ A, const float* __restrict__ W,
          const float* __restrict__ bias, float* __restrict__ C, int K) {
    constexpr int BM = 128;
    constexpr int BK = 32;
    constexpr int THREADS = 32 * WARPS_M * WARPS_N;
    constexpr int MT = (BM / WARPS_M) / 16;
    constexpr int NT = (BN / WARPS_N) / 8;

    __shared__ unsigned As[BM / 16][BK / 8][32][4];
    __shared__ unsigned Bs[BN / 8][BK / 16][32][4];

    const int tid  = threadIdx.x;
    const int lane = tid & 31;
    const int w    = tid >> 5;
    const int wm   = w / WARPS_N;
    const int wn   = w % WARPS_N;
    const int bm   = blockIdx.x * BM;
    const int bn   = blockIdx.y * BN;
    const int g    = lane >> 2;
    const int tig  = lane & 3;

    float acc[MT][NT][4];
#pragma unroll
    for (int i = 0; i < MT; i++)
#pragma unroll
        for (int j = 0; j < NT; j++)
#pragma unroll
            for (int r = 0; r < 4; r++) acc[i][j][r] = 0.f;

    for (int k0 = 0; k0 < K; k0 += BK) {
        constexpr int AV4 = BM * BK / 4;
#pragma unroll
        for (int it = 0; it < AV4 / THREADS; it++) {
            int idx = tid + it * THREADS;
            int row = idx >> 3;
            int c4  = idx & 7;
            float4 v = *(const float4*)(A + (size_t)(bm + row) * K + k0 + c4 * 4);
            int mt = row >> 4, r = row & 15;
            float vv[4] = {v.x, v.y, v.z, v.w};
#pragma unroll
            for (int j = 0; j < 4; j++) {
                int col = c4 * 4 + j;
                int kt = col >> 3, c = col & 7;
                As[mt][kt][(r & 7) * 4 + (c & 3)][(r >> 3) + 2 * (c >> 2)] = tf32_of(vv[j]);
            }
        }
        constexpr int BV4 = BN * BK / 4;
#pragma unroll
        for (int it = 0; it < (BV4 + THREADS - 1) / THREADS; it++) {
            int idx = tid + it * THREADS;
            if ((BV4 % THREADS == 0) || idx < BV4) {
                int n  = idx >> 3;
                int c4 = idx & 7;
                float4 v = *(const float4*)(W + (size_t)(bn + n) * K + k0 + c4 * 4);
                int nt = n >> 3, gg = n & 7;
                float vv[4] = {v.x, v.y, v.z, v.w};
#pragma unroll
                for (int j = 0; j < 4; j++) {
                    int k = c4 * 4 + j;
                    int kblk = k >> 4, kk = k & 15;
                    Bs[nt][kblk][gg * 4 + (kk & 3)][((kk >> 3) << 1) + ((kk & 7) >> 2)] = tf32_of(vv[j]);
                }
            }
        }
        __syncthreads();

#pragma unroll
        for (int kt = 0; kt < 4; kt++) {
            unsigned a[MT][4];
#pragma unroll
            for (int mt = 0; mt < MT; mt++)
                *(uint4*)a[mt] = *(const uint4*)&As[wm * MT + mt][kt][lane][0];
            unsigned b[NT][2];
#pragma unroll
            for (int nt = 0; nt < NT; nt++)
                *(uint2*)b[nt] = *(const uint2*)&Bs[wn * NT + nt][kt >> 1][lane][(kt & 1) * 2];
#pragma unroll
            for (int mt = 0; mt < MT; mt++)
#pragma unroll
                for (int nt = 0; nt < NT; nt++)
                    mma_tf32(acc[mt][nt], a[mt], b[nt]);
        }
        __syncthreads();
    }

#pragma unroll
    for (int mt = 0; mt < MT; mt++) {
#pragma unroll
        for (int nt = 0; nt < NT; nt++) {
            int col = bn + wn * (NT * 8) + nt * 8 + 2 * tig;
            int row0 = bm + wm * (MT * 16) + mt * 16 + g;
            float b0 = bias[col], b1 = bias[col + 1];
            float v0 = acc[mt][nt][0] + b0, v1 = acc[mt][nt][1] + b1;
            float v2 = acc[mt][nt][2] + b0, v3 = acc[mt][nt][3] + b1;
            if (RELU) {
                v0 = fmaxf(v0, 0.f); v1 = fmaxf(v1, 0.f);
                v2 = fmaxf(v2, 0.f); v3 = fmaxf(v3, 0.f);
            }
            int N_total = gridDim.y * BN;
            *(float2*)(C + (size_t)row0 * N_total + col)       = make_float2(v0, v1);
            *(float2*)(C + (size_t)(row0 + 8) * N_total + col) = make_float2(v2, v3);
        }
    }
}

// ---------------- scalar f32x2 GEMM (heads only, N=19) ----------------
template<int BM, int BN, int BK, int TM, int TN, bool RELU, bool NGUARD>
__global__ void __launch_bounds__((BM / TM) * (BN / TN))
gemm_kernel(const float* __restrict__ A, const float* __restrict__ W,
            const float* __restrict__ bias, float* __restrict__ C,
            int N, int K, int ldc) {
    constexpr int THREADS = (BM / TM) * (BN / TN);
    constexpr int BNQ = BN / TN;
    __shared__ __align__(16) float As[BK][BM + 4];
    __shared__ __align__(16) float Ws[BK][BN + 4];

    const int tid = threadIdx.x;
    const int bm = blockIdx.x * BM;
    const int bn = blockIdx.y * BN;
    const int tx = tid % BNQ;
    const int ty = tid / BNQ;

    ull acc2[TM / 2][TN];
#pragma unroll
    for (int i = 0; i < TM / 2; i++)
#pragma unroll
        for (int j = 0; j < TN; j++) acc2[i][j] = 0ull;

    for (int k0 = 0; k0 < K; k0 += BK) {
        constexpr int AV = BM * BK / 4;
#pragma unroll
        for (int i = 0; i < AV / THREADS; i++) {
            int idx = tid + i * THREADS;
            int row = idx / (BK / 4);
            int c4 = idx % (BK / 4);
            float4 v = *(const float4*)(A + (size_t)(bm + row) * K + k0 + c4 * 4);
            As[c4 * 4 + 0][row] = v.x;
            As[c4 * 4 + 1][row] = v.y;
            As[c4 * 4 + 2][row] = v.z;
            As[c4 * 4 + 3][row] = v.w;
        }
        constexpr int WV = BN * BK / 4;
#pragma unroll
        for (int i = 0; i < (WV + THREADS - 1) / THREADS; i++) {
            int idx = tid + i * THREADS;
            if ((WV % THREADS == 0) || idx < WV) {
                int row = idx / (BK / 4);
                int c4 = idx % (BK / 4);
                float4 v;
                if (!NGUARD || (bn + row) < N)
                    v = *(const float4*)(W + (size_t)(bn + row) * K + k0 + c4 * 4);
                else
                    v = make_float4(0.f, 0.f, 0.f, 0.f);
                Ws[c4 * 4 + 0][row] = v.x;
                Ws[c4 * 4 + 1][row] = v.y;
                Ws[c4 * 4 + 2][row] = v.z;
                Ws[c4 * 4 + 3][row] = v.w;
            }
        }
        __syncthreads();
#pragma unroll
        for (int kk = 0; kk < BK; kk++) {
            ull a2[TM / 2];
#pragma unroll
            for (int i2 = 0; i2 < TM / 2; i2++)
                a2[i2] = *(const ull*)&As[kk][ty * TM + 2 * i2];
            float br[TN];
#pragma unroll
            for (int j = 0; j < TN; j++) br[j] = Ws[kk][tx * TN + j];
            ull b2[TN];
#pragma unroll
            for (int j = 0; j < TN; j++) b2[j] = pack2(br[j], br[j]);
#pragma unroll
            for (int i2 = 0; i2 < TM / 2; i2++)
#pragma unroll
                for (int j = 0; j < TN; j++)
                    acc2[i2][j] = ffma2(a2[i2], b2[j], acc2[i2][j]);
        }
        __syncthreads();
    }
#pragma unroll
    for (int j = 0; j < TN; j++) {
        int n = bn + tx * TN + j;
        if (NGUARD && n >= N) continue;
        float bv = bias[n];
#pragma unroll
        for (int i2 = 0; i2 < TM / 2; i2++) {
            float v0, v1;
            unpack2(acc2[i2][j], v0, v1);
            v0 += bv; v1 += bv;
            if (RELU) { v0 = fmaxf(v0, 0.f); v1 = fmaxf(v1, 0.f); }
            C[(size_t)(bm + ty * TM + 2 * i2 + 0) * ldc + n] = v0;
            C[(size_t)(bm + ty * TM + 2 * i2 + 1) * ldc + n] = v1;
        }
    }
}

// ========== persistent tensor-core LSTM v3 ==========
// fp16 m16n8k16, all-resident gate-interleaved Whh, register-local update,
// ONE barrier per step, ping-pong h buffers.
// 128 CTAs x 512 threads (16 warps); CTA owns 8 batch rows for all 256 steps.
// Warp w owns tiles {2w, 2w+1}; thread (gg,tg) owns cells (j=8w+gg, b=2tg/2tg+1):
//   acc0 = [i(bA), i(bB), f(bA), f(bB)], acc1 = [g(bA), g(bB), o(bA), o(bB)]
#define LSTM4_SMEM (32 * 4096 + 2 * 2048)   // frags + hp ping-pong

__global__ void __launch_bounds__(512, 1)
lstm_tc_kernel(const float* __restrict__ xg, const float* __restrict__ done,
               const float* __restrict__ h0, const float* __restrict__ c0,
               float* __restrict__ hs, const unsigned* __restrict__ frag) {
    extern __shared__ unsigned smu[];
    unsigned* smA = smu;            // [32 tiles][8 ks][32 lanes][4]
    unsigned* hp0 = smu + 32768;    // [64 k2][8 b] fp16x2, phase 0
    unsigned* hp1 = hp0 + 512;      // phase 1

    const int tid  = threadIdx.x;
    const int w    = tid >> 5;
    const int lane = tid & 31;
    const int gg   = lane >> 2;
    const int tg   = lane & 3;
    const int bb0  = blockIdx.x * 8;

    // cooperative load of ALL fragment tiles (128 KB, coalesced)
    {
        const uint4* src = (const uint4*)frag;
        uint4* dst = (uint4*)smA;
        for (int i = tid; i < 8192; i += 512) dst[i] = src[i];
    }
    // h init into phase-0 buffer: h0 masked by done[0], fp16, packed by k-pairs
    {
        __half* hv = (__half*)hp0;
        for (int i = tid; i < 1024; i += 512) {
            int j = i >> 3, b = i & 7;
            float m = 1.f - done[bb0 + b];
            hv[(j >> 1) * 16 + 2 * b + (j & 1)] = __float2half_rn(h0[(bb0 + b) * 128 + j] * m);
        }
    }
    __syncthreads();

    const int j0 = 8 * w + gg;          // this thread's cell row
    const int bl = 2 * tg;              // local batch (pair base)
    const int bA = bb0 + bl;
    const int bB = bA + 1;
    const uint4* smT0 = (const uint4*)(smA + (2 * w) * 1024);
    const uint4* smT1 = (const uint4*)(smA + (2 * w + 1) * 1024);

    float cA, cB;
    {
        float mA = 1.f - done[bA], mB = 1.f - done[bB];
        cA = c0[bA * 128 + j0] * mA;
        cB = c0[bB * 128 + j0] * mB;
    }

    for (int step = 0; step < TT; ++step) {
        // xg for this thread's 2 cells x 4 gates (issued early; hides under mma)
        const float* xb  = xg + ((size_t)step * BB + bA) * 512;
        const float* xb2 = xb + 512;
        float xiA = xb[j0],        xiB = xb2[j0];
        float xfA = xb[j0 + 128],  xfB = xb2[j0 + 128];
        float xgA = xb[j0 + 256],  xgB = xb2[j0 + 256];
        float xoA = xb[j0 + 384],  xoB = xb2[j0 + 384];

        const unsigned* hc = (step & 1) ? hp1 : hp0;   // read phase
        unsigned*       hn = (step & 1) ? hp0 : hp1;   // write phase

        // ---- [i,f | g,o] = Whh-tiles @ h : 8 x k16 fp16 mma per tile ----
        float acc0[4] = {0.f, 0.f, 0.f, 0.f};
        float acc1[4] = {0.f, 0.f, 0.f, 0.f};
#pragma unroll
        for (int ks = 0; ks < 8; ks++) {
            unsigned b_[2];
            b_[0] = hc[(ks * 8 + tg) * 8 + gg];       // k = 16ks+2tg,   +1
            b_[1] = hc[(ks * 8 + 4 + tg) * 8 + gg];   // k = 16ks+8+2tg, +1
            uint4 a0 = smT0[ks * 32 + lane];
            uint4 a1 = smT1[ks * 32 + lane];
            mma_f16(acc0, (const unsigned*)&a0, b_);
            mma_f16(acc1, (const unsigned*)&a1, b_);
        }

        // next-step reset masks
        float mA2 = 1.f, mB2 = 1.f;
        if (step + 1 < TT) {
            mA2 = 1.f - done[(size_t)(step + 1) * BB + bA];
            mB2 = 1.f - done[(size_t)(step + 1) * BB + bB];
        }

        // ---- fully register-local cell update (no gate exchange) ----
        float iA = sigmoid_f(acc0[0] + xiA);
        float fA = sigmoid_f(acc0[2] + xfA);
        float gA = tanh_f   (acc1[0] + xgA);
        float oA = sigmoid_f(acc1[2] + xoA);
        cA = fA * cA + iA * gA;
        float hA = oA * tanh_f(cA);

        float iB = sigmoid_f(acc0[1] + xiB);
        float fB = sigmoid_f(acc0[3] + xfB);
        float gB = tanh_f   (acc1[1] + xgB);
        float oB = sigmoid_f(acc1[3] + xoB);
        cB = fB * cB + iB * gB;
        float hB = oB * tanh_f(cB);

        hs[((size_t)step * BB + bA) * 128 + j0] = hA;
        hs[((size_t)step * BB + bB) * 128 + j0] = hB;

        cA *= mA2;
        cB *= mB2;
        {
            __half* hv = (__half*)hn;
            int base = (j0 >> 1) * 16 + (j0 & 1);
            hv[base + 2 * bl]       = __float2half_rn(hA * mA2);
            hv[base + 2 * (bl + 1)] = __float2half_rn(hB * mB2);
        }
        __syncthreads();
    }
}

// ---------------- launch ----------------
extern "C" void kernel_launch(void* const* d_in, const int* in_sizes, int n_in,
                              void* d_out, int out_size) {
    const float* x    = (const float*)d_in[0];
    const float* done = (const float*)d_in[1];
    const float* h0   = (const float*)d_in[2];
    const float* c0   = (const float*)d_in[3];
    const float* W1   = (const float*)d_in[4];
    const float* b1   = (const float*)d_in[5];
    const float* W2   = (const float*)d_in[6];
    const float* b2   = (const float*)d_in[7];
    const float* W3   = (const float*)d_in[8];
    const float* b3   = (const float*)d_in[9];
    const float* Wih  = (const float*)d_in[10];
    const float* Whh  = (const float*)d_in[11];
    const float* bih  = (const float*)d_in[12];
    const float* bhh  = (const float*)d_in[13];
    const float* Wa   = (const float*)d_in[14];
    const float* ba   = (const float*)d_in[15];
    const float* Wc   = (const float*)d_in[16];
    const float* bc   = (const float*)d_in[17];
    float* out = (float*)d_out;

    float *h1, *h2, *h3, *xgp, *hsp, *bg, *whd, *bhd;
    unsigned* fragp;
    cudaGetSymbolAddress((void**)&h1,    g_h1);
    cudaGetSymbolAddress((void**)&h2,    g_h2);
    cudaGetSymbolAddress((void**)&h3,    g_h3);
    cudaGetSymbolAddress((void**)&xgp,   g_xg);
    cudaGetSymbolAddress((void**)&hsp,   g_hs);
    cudaGetSymbolAddress((void**)&fragp, g_WhhFragH);
    cudaGetSymbolAddress((void**)&bg,    g_bg);
    cudaGetSymbolAddress((void**)&whd,   g_Whead);
    cudaGetSymbolAddress((void**)&bhd,   g_bhead);

    static int smem_set = 0;
    if (!smem_set) {
        cudaFuncSetAttribute(lstm_tc_kernel,
                             cudaFuncAttributeMaxDynamicSharedMemorySize,
                             LSTM4_SMEM);
        smem_set = 1;
    }

    prepack_kernel<<<128, 256>>>(Whh, bih, bhh, Wa, ba, Wc, bc);

    // MLP encoder (tf32 tensor cores)
    tf32_gemm<128, 4, 2, true><<<dim3(TB / 128, 1), 256>>>(x,  W1, b1, h1, 128);
    tf32_gemm< 32, 8, 1, true><<<dim3(TB / 128, 1), 256>>>(h1, W2, b2, h2, 128);
    tf32_gemm<128, 4, 2, true><<<dim3(TB / 128, 1), 256>>>(h2, W3, b3, h3, 32);

    // xg = h3 @ Wih^T + (bih+bhh)
    tf32_gemm<256, 2, 4, false><<<dim3(TB / 128, 2), 256>>>(h3, Wih, bg, xgp, 128);

    // Sequential LSTM (fp16 tensor-core recurrence, one barrier/step)
    lstm_tc_kernel<<<128, 512, LSTM4_SMEM>>>(xgp, done, h0, c0, hsp, fragp);

    // Heads (fp32 scalar, N=19)
    gemm_kernel<128, 32, 32, 8, 2, false, true>
        <<<dim3(TB / 128, 1), 256>>>(hsp, whd, bhd, out, NOUT, 128, NOUT);
}

// round 16
// speedup vs baseline: 1.6994x; 1.5855x over previous
#include <cuda_runtime.h>
#include <cuda_fp16.h>
#include <math.h>

// Problem dims
#define TB   262144   // T*B = 256*1024
#define TT   256
#define BB   1024
#define NOUT 19

// ---------------- scratch (static device memory; no allocs) ----------------
__device__ float g_h1[TB * 128];
__device__ float g_h2[TB * 32];
__device__ float g_h3[TB * 128];
__device__ float g_xg[TB * 512];
__device__ float g_hs[TB * 128];
__device__ unsigned g_WhhFragH[32 * 8 * 32 * 4];  // [mtile][ks][lane][reg], fp16x2
__device__ float g_bg[512];
__device__ float g_Whead[NOUT * 128];
__device__ float g_bhead[NOUT];

// ---------------- packed f32x2 helpers ----------------
typedef unsigned long long ull;
__device__ __forceinline__ ull pack2(float lo, float hi) {
    ull r; asm("mov.b64 %0, {%1, %2};" : "=l"(r) : "f"(lo), "f"(hi)); return r;
}
__device__ __forceinline__ void unpack2(ull p, float& lo, float& hi) {
    asm("mov.b64 {%0, %1}, %2;" : "=f"(lo), "=f"(hi) : "l"(p));
}
__device__ __forceinline__ ull ffma2(ull a, ull b, ull c) {
    ull d; asm("fma.rn.f32x2 %0, %1, %2, %3;" : "=l"(d) : "l"(a), "l"(b), "l"(c));
    return d;
}

// ---------------- tf32 helpers (feedforward GEMMs) ----------------
__device__ __forceinline__ unsigned tf32_of(float f) {
    unsigned r; asm("cvt.rna.tf32.f32 %0, %1;" : "=r"(r) : "f"(f)); return r;
}
__device__ __forceinline__ void mma_tf32(float* d, const unsigned* a, const unsigned* b) {
    asm volatile(
        "mma.sync.aligned.m16n8k8.row.col.f32.tf32.tf32.f32 "
        "{%0,%1,%2,%3}, {%4,%5,%6,%7}, {%8,%9}, {%0,%1,%2,%3};"
        : "+f"(d[0]), "+f"(d[1]), "+f"(d[2]), "+f"(d[3])
        : "r"(a[0]), "r"(a[1]), "r"(a[2]), "r"(a[3]), "r"(b[0]), "r"(b[1]));
}

// ---------------- fp16 mma (LSTM recurrence) ----------------
__device__ __forceinline__ void mma_f16(float* d, const unsigned* a, const unsigned* b) {
    asm volatile(
        "mma.sync.aligned.m16n8k16.row.col.f32.f16.f16.f32 "
        "{%0,%1,%2,%3}, {%4,%5,%6,%7}, {%8,%9}, {%0,%1,%2,%3};"
        : "+f"(d[0]), "+f"(d[1]), "+f"(d[2]), "+f"(d[3])
        : "r"(a[0]), "r"(a[1]), "r"(a[2]), "r"(a[3]), "r"(b[0]), "r"(b[1]));
}

// ---------------- cp.async helpers ----------------
__device__ __forceinline__ unsigned smem_u32(const void* p) {
    return (unsigned)__cvta_generic_to_shared(p);
}
__device__ __forceinline__ void cp_async16(unsigned dst, const void* src) {
    asm volatile("cp.async.cg.shared.global [%0], [%1], 16;"
                 :: "r"(dst), "l"(src));
}
__device__ __forceinline__ void cp_commit() {
    asm volatile("cp.async.commit_group;");
}
__device__ __forceinline__ void cp_wait0() {
    asm volatile("cp.async.wait_group 0;" ::: "memory");
}

// ---------------- fast activations ----------------
__device__ __forceinline__ float sigmoid_f(float x) {
    return __fdividef(1.f, 1.f + __expf(-x));
}
__device__ __forceinline__ float tanh_f(float x) {
    float e = __expf(-2.f * fabsf(x));
    float r = __fdividef(1.f - e, 1.f + e);
    return copysignf(r, x);
}

// ---------------- prepack ----------------
// Gate-interleaved tile permutation for the LSTM:
//   tile 2w   rows 0..7  = i-gates j in [8w, 8w+8), rows 8..15 = f-gates same j
//   tile 2w+1 rows 0..7  = g-gates same j,          rows 8..15 = o-gates same j
// Fragment order (row-major A, fp16x2 per reg):
//   gg=lane>>2, tg=lane&3; lrow = gg + (r&1 ? 8:0); col = 16ks + 2tg + (r&2 ? 8:0)
__global__ void prepack_kernel(const float* __restrict__ Whh,
                               const float* __restrict__ bih,
                               const float* __restrict__ bhh,
                               const float* __restrict__ Wa,
                               const float* __restrict__ ba,
                               const float* __restrict__ Wc,
                               const float* __restrict__ bc) {
    int t = blockIdx.x * blockDim.x + threadIdx.x;
    int stride = gridDim.x * blockDim.x;
    for (int i = t; i < 32 * 8 * 32 * 4; i += stride) {
        int r    = i & 3;
        int lane = (i >> 2) & 31;
        int ks   = (i >> 7) & 7;
        int mt   = i >> 10;
        int gg = lane >> 2, tg = lane & 3;
        int lrow = gg + ((r & 1) ? 8 : 0);
        int col  = ks * 16 + 2 * tg + ((r & 2) ? 8 : 0);
        int wq   = mt >> 1;
        int half = mt & 1;
        int gate = (lrow < 8) ? (half ? 2 : 0) : (half ? 3 : 1);  // i,f,g,o blocks
        int row  = gate * 128 + wq * 8 + (lrow & 7);
        __half2 hv = __floats2half2_rn(Whh[row * 128 + col], Whh[row * 128 + col + 1]);
        g_WhhFragH[i] = *(unsigned*)&hv;
    }
    if (t < 512) g_bg[t] = bih[t] + bhh[t];
    for (int i = t; i < NOUT * 128; i += stride) {
        int n = i / 128, k = i % 128;
        g_Whead[i] = (n < 18) ? Wa[n * 128 + k] : Wc[k];
    }
    if (t < NOUT) g_bhead[t] = (t < 18) ? ba[t] : bc[0];
}

// ================= TF32 tensor-core GEMM (feedforward) =================
template<int BN, int WARPS_M, int WARPS_N, bool RELU>
__global__ void __launch_bounds__(32 * WARPS_M * WARPS_N, 2)
tf32_gemm(const float* __restrict__ A, const float* __restrict__ W,
          const float* __restrict__ bias, float* __restrict__ C, int K) {
    constexpr int BM = 128;
    constexpr int BK = 32;
    constexpr int THREADS = 32 * WARPS_M * WARPS_N;
    constexpr int MT = (BM / WARPS_M) / 16;
    constexpr int NT = (BN / WARPS_N) / 8;

    __shared__ unsigned As[BM / 16][BK / 8][32][4];
    __shared__ unsigned Bs[BN / 8][BK / 16][32][4];

    const int tid  = threadIdx.x;
    const int lane = tid & 31;
    const int w    = tid >> 5;
    const int wm   = w / WARPS_N;
    const int wn   = w % WARPS_N;
    const int bm   = blockIdx.x * BM;
    const int bn   = blockIdx.y * BN;
    const int g    = lane >> 2;
    const int tig  = lane & 3;

    float acc[MT][NT][4];
#pragma unroll
    for (int i = 0; i < MT; i++)
#pragma unroll
        for (int j = 0; j < NT; j++)
#pragma unroll
            for (int r = 0; r < 4; r++) acc[i][j][r] = 0.f;

    for (int k0 = 0; k0 < K; k0 += BK) {
        constexpr int AV4 = BM * BK / 4;
#pragma unroll
        for (int it = 0; it < AV4 / THREADS; it++) {
            int idx = tid + it * THREADS;
            int row = idx >> 3;
            int c4  = idx & 7;
            float4 v = *(const float4*)(A + (size_t)(bm + row) * K + k0 + c4 * 4);
            int mt = row >> 4, r = row & 15;
            float vv[4] = {v.x, v.y, v.z, v.w};
#pragma unroll
            for (int j = 0; j < 4; j++) {
                int col = c4 * 4 + j;
                int kt = col >> 3, c = col & 7;
                As[mt][kt][(r & 7) * 4 + (c & 3)][(r >> 3) + 2 * (c >> 2)] = tf32_of(vv[j]);
            }
        }
        constexpr int BV4 = BN * BK / 4;
#pragma unroll
        for (int it = 0; it < (BV4 + THREADS - 1) / THREADS; it++) {
            int idx = tid + it * THREADS;
            if ((BV4 % THREADS == 0) || idx < BV4) {
                int n  = idx >> 3;
                int c4 = idx & 7;
                float4 v = *(const float4*)(W + (size_t)(bn + n) * K + k0 + c4 * 4);
                int nt = n >> 3, gg = n & 7;
                float vv[4] = {v.x, v.y, v.z, v.w};
#pragma unroll
                for (int j = 0; j < 4; j++) {
                    int k = c4 * 4 + j;
                    int kblk = k >> 4, kk = k & 15;
                    Bs[nt][kblk][gg * 4 + (kk & 3)][((kk >> 3) << 1) + ((kk & 7) >> 2)] = tf32_of(vv[j]);
                }
            }
        }
        __syncthreads();

#pragma unroll
        for (int kt = 0; kt < 4; kt++) {
            unsigned a[MT][4];
#pragma unroll
            for (int mt = 0; mt < MT; mt++)
                *(uint4*)a[mt] = *(const uint4*)&As[wm * MT + mt][kt][lane][0];
            unsigned b[NT][2];
#pragma unroll
            for (int nt = 0; nt < NT; nt++)
                *(uint2*)b[nt] = *(const uint2*)&Bs[wn * NT + nt][kt >> 1][lane][(kt & 1) * 2];
#pragma unroll
            for (int mt = 0; mt < MT; mt++)
#pragma unroll
                for (int nt = 0; nt < NT; nt++)
                    mma_tf32(acc[mt][nt], a[mt], b[nt]);
        }
        __syncthreads();
    }

#pragma unroll
    for (int mt = 0; mt < MT; mt++) {
#pragma unroll
        for (int nt = 0; nt < NT; nt++) {
            int col = bn + wn * (NT * 8) + nt * 8 + 2 * tig;
            int row0 = bm + wm * (MT * 16) + mt * 16 + g;
            float b0 = bias[col], b1 = bias[col + 1];
            float v0 = acc[mt][nt][0] + b0, v1 = acc[mt][nt][1] + b1;
            float v2 = acc[mt][nt][2] + b0, v3 = acc[mt][nt][3] + b1;
            if (RELU) {
                v0 = fmaxf(v0, 0.f); v1 = fmaxf(v1, 0.f);
                v2 = fmaxf(v2, 0.f); v3 = fmaxf(v3, 0.f);
            }
            int N_total = gridDim.y * BN;
            *(float2*)(C + (size_t)row0 * N_total + col)       = make_float2(v0, v1);
            *(float2*)(C + (size_t)(row0 + 8) * N_total + col) = make_float2(v2, v3);
        }
    }
}

// ---------------- scalar f32x2 GEMM (heads only, N=19) ----------------
template<int BM, int BN, int BK, int TM, int TN, bool RELU, bool NGUARD>
__global__ void __launch_bounds__((BM / TM) * (BN / TN))
gemm_kernel(const float* __restrict__ A, const float* __restrict__ W,
            const float* __restrict__ bias, float* __restrict__ C,
            int N, int K, int ldc) {
    constexpr int THREADS = (BM / TM) * (BN / TN);
    constexpr int BNQ = BN / TN;
    __shared__ __align__(16) float As[BK][BM + 4];
    __shared__ __align__(16) float Ws[BK][BN + 4];

    const int tid = threadIdx.x;
    const int bm = blockIdx.x * BM;
    const int bn = blockIdx.y * BN;
    const int tx = tid % BNQ;
    const int ty = tid / BNQ;

    ull acc2[TM / 2][TN];
#pragma unroll
    for (int i = 0; i < TM / 2; i++)
#pragma unroll
        for (int j = 0; j < TN; j++) acc2[i][j] = 0ull;

    for (int k0 = 0; k0 < K; k0 += BK) {
        constexpr int AV = BM * BK / 4;
#pragma unroll
        for (int i = 0; i < AV / THREADS; i++) {
            int idx = tid + i * THREADS;
            int row = idx / (BK / 4);
            int c4 = idx % (BK / 4);
            float4 v = *(const float4*)(A + (size_t)(bm + row) * K + k0 + c4 * 4);
            As[c4 * 4 + 0][row] = v.x;
            As[c4 * 4 + 1][row] = v.y;
            As[c4 * 4 + 2][row] = v.z;
            As[c4 * 4 + 3][row] = v.w;
        }
        constexpr int WV = BN * BK / 4;
#pragma unroll
        for (int i = 0; i < (WV + THREADS - 1) / THREADS; i++) {
            int idx = tid + i * THREADS;
            if ((WV % THREADS == 0) || idx < WV) {
                int row = idx / (BK / 4);
                int c4 = idx % (BK / 4);
                float4 v;
                if (!NGUARD || (bn + row) < N)
                    v = *(const float4*)(W + (size_t)(bn + row) * K + k0 + c4 * 4);
                else
                    v = make_float4(0.f, 0.f, 0.f, 0.f);
                Ws[c4 * 4 + 0][row] = v.x;
                Ws[c4 * 4 + 1][row] = v.y;
                Ws[c4 * 4 + 2][row] = v.z;
                Ws[c4 * 4 + 3][row] = v.w;
            }
        }
        __syncthreads();
#pragma unroll
        for (int kk = 0; kk < BK; kk++) {
            ull a2[TM / 2];
#pragma unroll
            for (int i2 = 0; i2 < TM / 2; i2++)
                a2[i2] = *(const ull*)&As[kk][ty * TM + 2 * i2];
            float br[TN];
#pragma unroll
            for (int j = 0; j < TN; j++) br[j] = Ws[kk][tx * TN + j];
            ull b2[TN];
#pragma unroll
            for (int j = 0; j < TN; j++) b2[j] = pack2(br[j], br[j]);
#pragma unroll
            for (int i2 = 0; i2 < TM / 2; i2++)
#pragma unroll
                for (int j = 0; j < TN; j++)
                    acc2[i2][j] = ffma2(a2[i2], b2[j], acc2[i2][j]);
        }
        __syncthreads();
    }
#pragma unroll
    for (int j = 0; j < TN; j++) {
        int n = bn + tx * TN + j;
        if (NGUARD && n >= N) continue;
        float bv = bias[n];
#pragma unroll
        for (int i2 = 0; i2 < TM / 2; i2++) {
            float v0, v1;
            unpack2(acc2[i2][j], v0, v1);
            v0 += bv; v1 += bv;
            if (RELU) { v0 = fmaxf(v0, 0.f); v1 = fmaxf(v1, 0.f); }
            C[(size_t)(bm + ty * TM + 2 * i2 + 0) * ldc + n] = v0;
            C[(size_t)(bm + ty * TM + 2 * i2 + 1) * ldc + n] = v1;
        }
    }
}

// ========== persistent tensor-core LSTM v4 ==========
// v3 (fp16 m16n8k16, gate-interleaved resident Whh, register-local update,
// one barrier/step) + cp.async double-buffered xg staging:
//   step t's 16 KB xg slice is streamed into smem during step t-1 by
//   cooperative cp.async.16 (2 per thread, zero register cost), drained right
//   before the end-of-step barrier. x reads become conflict-free LDS
//   (row stride 516 floats: bank = (8*tg + gg) mod 32, all distinct).
#define XPH  (8 * 516)                               // floats per xg phase
#define LSTM5_SMEM (32 * 4096 + 2 * 2048 + 2 * XPH * 4)

__global__ void __launch_bounds__(512, 1)
lstm_tc_kernel(const float* __restrict__ xg, const float* __restrict__ done,
               const float* __restrict__ h0, const float* __restrict__ c0,
               float* __restrict__ hs, const unsigned* __restrict__ frag) {
    extern __shared__ unsigned smu[];
    unsigned* smA = smu;            // [32 tiles][8 ks][32 lanes][4]
    unsigned* hp0 = smu + 32768;    // [64 k2][8 b] fp16x2, phase 0
    unsigned* hp1 = hp0 + 512;      // phase 1
    float*    xbuf = (float*)(hp1 + 512);   // [2][8 b][516] xg staging

    const int tid  = threadIdx.x;
    const int w    = tid >> 5;
    const int lane = tid & 31;
    const int gg   = lane >> 2;
    const int tg   = lane & 3;
    const int bb0  = blockIdx.x * 8;

    // cp.async chunk mapping: chunk c in [0,1024): b = c>>7, off = (c&127)*4
    const int c0b = tid >> 7,        c0o = (tid & 127) * 4;
    const int c1b = 4 + (tid >> 7),  c1o = c0o;

    // cooperative load of ALL fragment tiles (128 KB, coalesced)
    {
        const uint4* src = (const uint4*)frag;
        uint4* dst = (uint4*)smA;
        for (int i = tid; i < 8192; i += 512) dst[i] = src[i];
    }
    // h init into phase-0 buffer: h0 masked by done[0], fp16, packed by k-pairs
    {
        __half* hv = (__half*)hp0;
        for (int i = tid; i < 1024; i += 512) {
            int j = i >> 3, b = i & 7;
            float m = 1.f - done[bb0 + b];
            hv[(j >> 1) * 16 + 2 * b + (j & 1)] = __float2half_rn(h0[(bb0 + b) * 128 + j] * m);
        }
    }
    // prologue: stage step-0 xg slice into phase 0
    {
        const float* src = xg + (size_t)bb0 * 512;
        cp_async16(smem_u32(xbuf + c0b * 516 + c0o), src + c0b * 512 + c0o);
        cp_async16(smem_u32(xbuf + c1b * 516 + c1o), src + c1b * 512 + c1o);
        cp_commit();
        cp_wait0();
    }
    __syncthreads();

    const int j0 = 8 * w + gg;          // this thread's cell row
    const int bl = 2 * tg;              // local batch (pair base)
    const int bA = bb0 + bl;
    const int bB = bA + 1;
    const uint4* smT0 = (const uint4*)(smA + (2 * w) * 1024);
    const uint4* smT1 = (const uint4*)(smA + (2 * w + 1) * 1024);

    float cA, cB;
    {
        float mA = 1.f - done[bA], mB = 1.f - done[bB];
        cA = c0[bA * 128 + j0] * mA;
        cB = c0[bB * 128 + j0] * mB;
    }

    for (int step = 0; step < TT; ++step) {
        const float* xcur = xbuf + (step & 1) * XPH;

        // stage step+1's xg slice into the other phase (zero-register prefetch)
        if (step + 1 < TT) {
            float* xnxt = xbuf + ((step + 1) & 1) * XPH;
            const float* src = xg + ((size_t)(step + 1) * BB + bb0) * 512;
            cp_async16(smem_u32(xnxt + c0b * 516 + c0o), src + c0b * 512 + c0o);
            cp_async16(smem_u32(xnxt + c1b * 516 + c1o), src + c1b * 512 + c1o);
            cp_commit();
        }

        const unsigned* hc = (step & 1) ? hp1 : hp0;   // read phase
        unsigned*       hn = (step & 1) ? hp0 : hp1;   // write phase

        // ---- [i,f | g,o] = Whh-tiles @ h : 8 x k16 fp16 mma per tile ----
        float acc0[4] = {0.f, 0.f, 0.f, 0.f};
        float acc1[4] = {0.f, 0.f, 0.f, 0.f};
#pragma unroll
        for (int ks = 0; ks < 8; ks++) {
            unsigned b_[2];
            b_[0] = hc[(ks * 8 + tg) * 8 + gg];       // k = 16ks+2tg,   +1
            b_[1] = hc[(ks * 8 + 4 + tg) * 8 + gg];   // k = 16ks+8+2tg, +1
            uint4 a0 = smT0[ks * 32 + lane];
            uint4 a1 = smT1[ks * 32 + lane];
            mma_f16(acc0, (const unsigned*)&a0, b_);
            mma_f16(acc1, (const unsigned*)&a1, b_);
        }

        // next-step reset masks
        float mA2 = 1.f, mB2 = 1.f;
        if (step + 1 < TT) {
            mA2 = 1.f - done[(size_t)(step + 1) * BB + bA];
            mB2 = 1.f - done[(size_t)(step + 1) * BB + bB];
        }

        // x values from staged smem (conflict-free: bank = 8*tg + gg)
        const float* xA = xcur + bl * 516 + j0;
        const float* xB = xA + 516;
        float xiA = xA[0], xfA = xA[128], xgA = xA[256], xoA = xA[384];
        float xiB = xB[0], xfB = xB[128], xgB = xB[256], xoB = xB[384];

        // ---- fully register-local cell update (no gate exchange) ----
        float iA = sigmoid_f(acc0[0] + xiA);
        float fA = sigmoid_f(acc0[2] + xfA);
        float gA = tanh_f   (acc1[0] + xgA);
        float oA = sigmoid_f(acc1[2] + xoA);
        cA = fA * cA + iA * gA;
        float hA = oA * tanh_f(cA);

        float iB = sigmoid_f(acc0[1] + xiB);
        float fB = sigmoid_f(acc0[3] + xfB);
        float gB = tanh_f   (acc1[1] + xgB);
        float oB = sigmoid_f(acc1[3] + xoB);
        cB = fB * cB + iB * gB;
        float hB = oB * tanh_f(cB);

        hs[((size_t)step * BB + bA) * 128 + j0] = hA;
        hs[((size_t)step * BB + bB) * 128 + j0] = hB;

        cA *= mA2;
        cB *= mB2;
        {
            __half* hv = (__half*)hn;
            int base = (j0 >> 1) * 16 + (j0 & 1);
            hv[base + 2 * bl]       = __float2half_rn(hA * mA2);
            hv[base + 2 * (bl + 1)] = __float2half_rn(hB * mB2);
        }

        // drain step+1's xg group (issued ~a full step ago), then barrier
        cp_wait0();
        __syncthreads();
    }
}

// ---------------- launch ----------------
extern "C" void kernel_launch(void* const* d_in, const int* in_sizes, int n_in,
                              void* d_out, int out_size) {
    const float* x    = (const float*)d_in[0];
    const float* done = (const float*)d_in[1];
    const float* h0   = (const float*)d_in[2];
    const float* c0   = (const float*)d_in[3];
    const float* W1   = (const float*)d_in[4];
    const float* b1   = (const float*)d_in[5];
    const float* W2   = (const float*)d_in[6];
    const float* b2   = (const float*)d_in[7];
    const float* W3   = (const float*)d_in[8];
    const float* b3   = (const float*)d_in[9];
    const float* Wih  = (const float*)d_in[10];
    const float* Whh  = (const float*)d_in[11];
    const float* bih  = (const float*)d_in[12];
    const float* bhh  = (const float*)d_in[13];
    const float* Wa   = (const float*)d_in[14];
    const float* ba   = (const float*)d_in[15];
    const float* Wc   = (const float*)d_in[16];
    const float* bc   = (const float*)d_in[17];
    float* out = (float*)d_out;

    float *h1, *h2, *h3, *xgp, *hsp, *bg, *whd, *bhd;
    unsigned* fragp;
    cudaGetSymbolAddress((void**)&h1,    g_h1);
    cudaGetSymbolAddress((void**)&h2,    g_h2);
    cudaGetSymbolAddress((void**)&h3,    g_h3);
    cudaGetSymbolAddress((void**)&xgp,   g_xg);
    cudaGetSymbolAddress((void**)&hsp,   g_hs);
    cudaGetSymbolAddress((void**)&fragp, g_WhhFragH);
    cudaGetSymbolAddress((void**)&bg,    g_bg);
    cudaGetSymbolAddress((void**)&whd,   g_Whead);
    cudaGetSymbolAddress((void**)&bhd,   g_bhead);

    static int smem_set = 0;
    if (!smem_set) {
        cudaFuncSetAttribute(lstm_tc_kernel,
                             cudaFuncAttributeMaxDynamicSharedMemorySize,
                             LSTM5_SMEM);
        smem_set = 1;
    }

    prepack_kernel<<<128, 256>>>(Whh, bih, bhh, Wa, ba, Wc, bc);

    // MLP encoder (tf32 tensor cores)
    tf32_gemm<128, 4, 2, true><<<dim3(TB / 128, 1), 256>>>(x,  W1, b1, h1, 128);
    tf32_gemm< 32, 8, 1, true><<<dim3(TB / 128, 1), 256>>>(h1, W2, b2, h2, 128);
    tf32_gemm<128, 4, 2, true><<<dim3(TB / 128, 1), 256>>>(h2, W3, b3, h3, 32);

    // xg = h3 @ Wih^T + (bih+bhh)
    tf32_gemm<256, 2, 4, false><<<dim3(TB / 128, 2), 256>>>(h3, Wih, bg, xgp, 128);

    // Sequential LSTM (fp16 tensor-core recurrence, cp.async xg staging)
    lstm_tc_kernel<<<128, 512, LSTM5_SMEM>>>(xgp, done, h0, c0, hsp, fragp);

    // Heads (fp32 scalar, N=19)
    gemm_kernel<128, 32, 32, 8, 2, false, true>
        <<<dim3(TB / 128, 1), 256>>>(hsp, whd, bhd, out, NOUT, 128, NOUT);
}